// round 6
// baseline (speedup 1.0000x reference)
#include <cuda_runtime.h>
#include <cstdint>

// out[g] = sigmoid(Z_g @ Z_g^T), G=128, N=512, D=256, fp32.
// R6: int8 IMMA (mma.m16n8k32.s8) two-digit fixed point, per-row scale:
//   z = s*(a + v/128), a,v in s8; Z Z^T = s_i s_j (AA^T + (AV^T + VA^T)/128)
// exact int32 accumulation; dropped VV^T/16384 ~ 1e-3 logit rms.
// 512-thread CTA, 128x128 tile, warp-tile 32x32, 3-stage cp.async ring,
// symmetry over 10 of 16 tile pairs.

namespace {
constexpr int NN = 512;
constexpr int ND = 256;
constexpr int BM = 128;
constexpr int NPAIR = 10;
constexpr int BKC = 64;                   // int8 k-elems per chunk (64 B/row)
constexpr int NCH = ND / BKC;             // 4 chunks
constexpr int SMATC = BM * BKC;           // 8192 B per operand mat per chunk
constexpr int SSTAGE = 4 * SMATC;         // 32768 B (Aa, Av, Ba, Bv)
constexpr int NSTAGE = 3;
constexpr int SMEM_DYN = NSTAGE * SSTAGE; // 98304 B
}

__constant__ int c_it[NPAIR] = {0,0,0,0,1,1,1,2,2,3};
__constant__ int c_jt[NPAIR] = {0,1,2,3,1,2,3,2,3,3};

__device__ __align__(16) int8_t g_a[(size_t)128 * 512 * 256];  // 16MB hi digit
__device__ __align__(16) int8_t g_v[(size_t)128 * 512 * 256];  // 16MB lo digit
__device__ float g_s[128 * 512];                               // per-row scale

__device__ __forceinline__ uint32_t cvta_smem(const void* p) {
    uint32_t a;
    asm("{ .reg .u64 t; cvta.to.shared.u64 t, %1; cvt.u32.u64 %0, t; }"
        : "=r"(a) : "l"(p));
    return a;
}

// swizzled byte offset: 64B rows, 4 x 16B segs
__device__ __forceinline__ uint32_t swz(int row, int seg) {
    return (uint32_t)(row * 64 + ((seg ^ ((row >> 1) & 3)) << 4));
}

__device__ __forceinline__ void ldsm4(uint32_t* r, uint32_t addr) {
    asm volatile("ldmatrix.sync.aligned.m8n8.x4.shared.b16 {%0,%1,%2,%3}, [%4];"
                 : "=r"(r[0]), "=r"(r[1]), "=r"(r[2]), "=r"(r[3]) : "r"(addr));
}

__device__ __forceinline__ void imma16832(int* c, const uint32_t* a,
                                          uint32_t b0, uint32_t b1) {
    asm volatile(
        "mma.sync.aligned.m16n8k32.row.col.s32.s8.s8.s32 "
        "{%0,%1,%2,%3}, {%4,%5,%6,%7}, {%8,%9}, {%0,%1,%2,%3};"
        : "+r"(c[0]), "+r"(c[1]), "+r"(c[2]), "+r"(c[3])
        : "r"(a[0]), "r"(a[1]), "r"(a[2]), "r"(a[3]), "r"(b0), "r"(b1));
}

__device__ __forceinline__ float fast_sigmoid(float x) {
    float e = __expf(-x);
    return __fdividef(1.0f, 1.0f + e);
}

// ---------------- pre-pass: fp32 -> per-row-scaled two-digit int8 ----------------
__global__ __launch_bounds__(256)
void quant_kernel(const float* __restrict__ z) {
    const int warp = threadIdx.x >> 5;
    const int lane = threadIdx.x & 31;
    const int row  = blockIdx.x * 8 + warp;
    const size_t base = (size_t)row * ND + lane * 8;

    float x[8];
    *(float4*)&x[0] = *(const float4*)(z + base);
    *(float4*)&x[4] = *(const float4*)(z + base + 4);

    float m = 0.0f;
#pragma unroll
    for (int i = 0; i < 8; i++) m = fmaxf(m, fabsf(x[i]));
#pragma unroll
    for (int d = 16; d > 0; d >>= 1)
        m = fmaxf(m, __shfl_xor_sync(0xffffffffu, m, d));

    const float s   = m * (1.0f / 127.0f);
    const float inv = (m > 0.0f) ? (127.0f / m) : 0.0f;

    uint32_t pa[2] = {0, 0}, pv[2] = {0, 0};
#pragma unroll
    for (int i = 0; i < 8; i++) {
        float t  = x[i] * inv;
        float af = rintf(t);
        int   ai = (int)af;
        int   vi = (int)rintf((t - af) * 128.0f);
        pa[i >> 2] |= (uint32_t)(ai & 0xff) << ((i & 3) * 8);
        pv[i >> 2] |= (uint32_t)(vi & 0xff) << ((i & 3) * 8);
    }
    ((uint2*)g_a)[base >> 3] = make_uint2(pa[0], pa[1]);
    ((uint2*)g_v)[base >> 3] = make_uint2(pv[0], pv[1]);
    if (lane == 0) g_s[row] = s;
}

// ---------------- GEMM + sigmoid ----------------
__global__ __launch_bounds__(512, 1)
void gemm_kernel(float* __restrict__ out) {
    extern __shared__ char smem[];
    __shared__ float sScA[128], sScB[128];

    const int tid  = threadIdx.x;
    const int lane = tid & 31;
    const int wid  = tid >> 5;
    const int wm   = wid >> 2;   // 32-row block (0..3)
    const int wn   = wid & 3;    // 32-col block (0..3)

    const int g  = blockIdx.y;
    const int it = c_it[blockIdx.x];
    const int jt = c_jt[blockIdx.x];
    const bool diag = (it == jt);

    const int8_t* __restrict__ Aa = g_a + ((size_t)g * NN + it * BM) * ND;
    const int8_t* __restrict__ Av = g_v + ((size_t)g * NN + it * BM) * ND;
    const int8_t* __restrict__ Ba = g_a + ((size_t)g * NN + jt * BM) * ND;
    const int8_t* __restrict__ Bv = g_v + ((size_t)g * NN + jt * BM) * ND;

    if (tid < 128)
        sScA[tid] = g_s[g * NN + it * BM + tid];
    else if (tid < 256)
        sScB[tid - 128] = g_s[g * NN + jt * BM + (tid - 128)];

    const uint32_t s32 = cvta_smem(smem);
    const uint32_t ba_base = diag ? 0u : 2u * SMATC;
    const uint32_t bv_base = diag ? 1u * SMATC : 3u * SMATC;
    const int nmat = diag ? 2 : 4;

    const int ld_row = tid >> 2;   // 0..127
    const int ld_seg = tid & 3;

    int c_hi[2][4][4], c_mid[2][4][4];
#pragma unroll
    for (int mt = 0; mt < 2; mt++)
#pragma unroll
        for (int nt = 0; nt < 4; nt++)
#pragma unroll
            for (int q = 0; q < 4; q++) { c_hi[mt][nt][q] = 0; c_mid[mt][nt][q] = 0; }

    // ldmatrix lane addressing (shared by A and B)
    const int lrow_off = (lane & 7) + ((lane >> 3) & 1) * 8;
    const int lseg_off = lane >> 4;

    auto issue_chunk = [&](int ch) {
        const uint32_t sb = s32 + (ch % NSTAGE) * SSTAGE;
        const int kofs = ch * BKC;
        for (int mat = 0; mat < nmat; mat++) {
            const int8_t* src =
                (mat == 0) ? Aa : (mat == 1) ? Av : (mat == 2) ? Ba : Bv;
            const uint32_t dst = sb + mat * SMATC + swz(ld_row, ld_seg);
            const void* sp = src + (size_t)ld_row * ND + kofs + ld_seg * 16;
            asm volatile("cp.async.cg.shared.global [%0], [%1], 16;"
                         :: "r"(dst), "l"(sp) : "memory");
        }
    };

    issue_chunk(0);
    asm volatile("cp.async.commit_group;" ::: "memory");
    issue_chunk(1);
    asm volatile("cp.async.commit_group;" ::: "memory");

    for (int ch = 0; ch < NCH; ch++) {
        asm volatile("cp.async.wait_group 1;" ::: "memory");
        __syncthreads();
        if (ch + 2 < NCH) issue_chunk(ch + 2);
        asm volatile("cp.async.commit_group;" ::: "memory");

        const uint32_t sb = s32 + (ch % NSTAGE) * SSTAGE;
#pragma unroll
        for (int h = 0; h < 2; h++) {
            uint32_t aa[2][4], av[2][4], ba[2][4], bv[2][4];
            const int seg = 2 * h + lseg_off;
#pragma unroll
            for (int mt = 0; mt < 2; mt++) {
                const int row = wm * 32 + mt * 16 + lrow_off;
                ldsm4(aa[mt], sb + 0 * SMATC + swz(row, seg));
                ldsm4(av[mt], sb + 1 * SMATC + swz(row, seg));
            }
#pragma unroll
            for (int q = 0; q < 2; q++) {
                const int row = wn * 32 + q * 16 + lrow_off;
                ldsm4(ba[q], sb + ba_base + swz(row, seg));
                ldsm4(bv[q], sb + bv_base + swz(row, seg));
            }
            // b-frag for nt: q = nt>>1, regs {[nt&1], [2+(nt&1)]}
            // sweep 1: Aa * Ba -> c_hi
#pragma unroll
            for (int mt = 0; mt < 2; mt++)
#pragma unroll
                for (int nt = 0; nt < 4; nt++)
                    imma16832(c_hi[mt][nt], aa[mt],
                              ba[nt >> 1][nt & 1], ba[nt >> 1][2 + (nt & 1)]);
            // sweep 2: Av * Ba -> c_mid
#pragma unroll
            for (int mt = 0; mt < 2; mt++)
#pragma unroll
                for (int nt = 0; nt < 4; nt++)
                    imma16832(c_mid[mt][nt], av[mt],
                              ba[nt >> 1][nt & 1], ba[nt >> 1][2 + (nt & 1)]);
            // sweep 3: Aa * Bv -> c_mid
#pragma unroll
            for (int mt = 0; mt < 2; mt++)
#pragma unroll
                for (int nt = 0; nt < 4; nt++)
                    imma16832(c_mid[mt][nt], aa[mt],
                              bv[nt >> 1][nt & 1], bv[nt >> 1][2 + (nt & 1)]);
        }
    }

    // ---- epilogue: combine digits, sigmoid -> smem -> stores ----
    __syncthreads();
    float* sC = (float*)smem;  // [128][132] = 67584 B <= 98304 B
    const int er = wm * 32 + (lane >> 2);
    const int ec = wn * 32 + 2 * (lane & 3);
#pragma unroll
    for (int mt = 0; mt < 2; mt++)
#pragma unroll
        for (int nt = 0; nt < 4; nt++) {
            const int r0 = er + mt * 16;
            const int cc = ec + nt * 8;
            const float sB0 = sScB[cc], sB1 = sScB[cc + 1];
#pragma unroll
            for (int half = 0; half < 2; half++) {
                const int r = r0 + half * 8;
                const float sA = sScA[r];
                const float l0 = sA * sB0 *
                    ((float)c_hi[mt][nt][2 * half] +
                     (float)c_mid[mt][nt][2 * half] * 0.0078125f);
                const float l1 = sA * sB1 *
                    ((float)c_hi[mt][nt][2 * half + 1] +
                     (float)c_mid[mt][nt][2 * half + 1] * 0.0078125f);
                sC[r * 132 + cc]     = fast_sigmoid(l0);
                sC[r * 132 + cc + 1] = fast_sigmoid(l1);
            }
        }
    __syncthreads();

    const int rbase = it * BM, cbase = jt * BM;
    {
        const int r  = tid >> 2;
        const int cq = (tid & 3) * 32;
        float* dst = out + ((size_t)g * NN + rbase + r) * NN + cbase + cq;
        const float* srcr = sC + r * 132 + cq;
#pragma unroll
        for (int q = 0; q < 8; q++)
            ((float4*)dst)[q] = ((const float4*)srcr)[q];
    }
    if (!diag) {
        const int col = tid >> 2;
        const int rq  = (tid & 3) * 32;
        float* dst = out + ((size_t)g * NN + cbase + col) * NN + rbase + rq;
#pragma unroll
        for (int q = 0; q < 8; q++) {
            float4 w;
            w.x = sC[(rq + q * 4 + 0) * 132 + col];
            w.y = sC[(rq + q * 4 + 1) * 132 + col];
            w.z = sC[(rq + q * 4 + 2) * 132 + col];
            w.w = sC[(rq + q * 4 + 3) * 132 + col];
            ((float4*)dst)[q] = w;
        }
    }
}

extern "C" void kernel_launch(void* const* d_in, const int* in_sizes, int n_in,
                              void* d_out, int out_size) {
    const float* z = (const float*)d_in[0];
    float* out = (float*)d_out;
    quant_kernel<<<8192, 256>>>(z);  // 65536 rows / 8 per block
    cudaFuncSetAttribute(gemm_kernel, cudaFuncAttributeMaxDynamicSharedMemorySize,
                         SMEM_DYN);
    dim3 grid(NPAIR, 128);
    gemm_kernel<<<grid, 512, SMEM_DYN>>>(out);
}

// round 8
// speedup vs baseline: 2.5637x; 2.5637x over previous
#include <cuda_runtime.h>
#include <cuda_fp16.h>
#include <cstdint>

// out[g] = sigmoid(Z_g @ Z_g^T), G=128, N=512, D=256, fp32.
// R8: fp16 symmetrized 2-product scheme on mma.m16n8k16.f16:
//   h = fp16(z), b2 = fp16(2z - h)  =>  0.5*(H B2^T + B2 H^T) ~= Z Z^T
// Both products share one accumulator orientation. Diagonal tiles: single
// product D = H B2^T, symmetrized via smem (0.5*(D + D^T)).
// Fix vs R7: convert_kernel grid 4096 -> 8192 (was covering only half of z).

namespace {
constexpr int NN = 512;
constexpr int ND = 256;
constexpr int BM = 128;
constexpr int NPAIR = 10;
constexpr int BKC = 32;                  // k elems per chunk (64B rows)
constexpr int NCH = ND / BKC;            // 8 chunks
constexpr int SMATC = BM * BKC * 2;      // 8192 B per operand mat per chunk
constexpr int SSTAGE = 4 * SMATC;        // 32768 B
constexpr int NSTAGE = 3;
constexpr int SMEM_DYN = NSTAGE * SSTAGE;  // 98304 B
}

__constant__ int c_it[NPAIR] = {0,0,0,0,1,1,1,2,2,3};
__constant__ int c_jt[NPAIR] = {0,1,2,3,1,2,3,2,3,3};

__device__ __align__(16) __half g_h [(size_t)128 * 512 * 256];  // 32MB fp16(z)
__device__ __align__(16) __half g_b2[(size_t)128 * 512 * 256];  // 32MB fp16(2z-h)

__device__ __forceinline__ uint32_t cvta_smem(const void* p) {
    uint32_t a;
    asm("{ .reg .u64 t; cvta.to.shared.u64 t, %1; cvt.u32.u64 %0, t; }"
        : "=r"(a) : "l"(p));
    return a;
}

// swizzled byte offset: 64B rows, 4 x 16B segs
__device__ __forceinline__ uint32_t swz(int row, int seg) {
    return (uint32_t)(row * 64 + ((seg ^ ((row >> 1) & 3)) << 4));
}

__device__ __forceinline__ void ldsm4(uint32_t* r, uint32_t addr) {
    asm volatile("ldmatrix.sync.aligned.m8n8.x4.shared.b16 {%0,%1,%2,%3}, [%4];"
                 : "=r"(r[0]), "=r"(r[1]), "=r"(r[2]), "=r"(r[3]) : "r"(addr));
}

__device__ __forceinline__ void mma16816(float* c, const uint32_t* a,
                                         uint32_t b0, uint32_t b1) {
    asm volatile(
        "mma.sync.aligned.m16n8k16.row.col.f32.f16.f16.f32 "
        "{%0,%1,%2,%3}, {%4,%5,%6,%7}, {%8,%9}, {%0,%1,%2,%3};"
        : "+f"(c[0]), "+f"(c[1]), "+f"(c[2]), "+f"(c[3])
        : "r"(a[0]), "r"(a[1]), "r"(a[2]), "r"(a[3]), "r"(b0), "r"(b1));
}

__device__ __forceinline__ float fast_sigmoid(float x) {
    float e = __expf(-x);
    return __fdividef(1.0f, 1.0f + e);
}

// ---------------- pre-pass: fp32 -> fp16 h, fp16 b2 = fp16(2z - h) ----------------
__global__ __launch_bounds__(256)
void convert_kernel(const float* __restrict__ z) {
    const size_t base = ((size_t)blockIdx.x * blockDim.x + threadIdx.x) * 8;
    float x[8];
    *(float4*)&x[0] = *(const float4*)(z + base);
    *(float4*)&x[4] = *(const float4*)(z + base + 4);

    uint32_t ph[4], pb[4];
#pragma unroll
    for (int q = 0; q < 4; q++) {
        __half h0 = __float2half_rn(x[2 * q]);
        __half h1 = __float2half_rn(x[2 * q + 1]);
        float  f0 = __half2float(h0);
        float  f1 = __half2float(h1);
        __half b0 = __float2half_rn(2.0f * x[2 * q] - f0);
        __half b1 = __float2half_rn(2.0f * x[2 * q + 1] - f1);
        __half2 hp = __halves2half2(h0, h1);
        __half2 bp = __halves2half2(b0, b1);
        ph[q] = *(uint32_t*)&hp;
        pb[q] = *(uint32_t*)&bp;
    }
    ((uint4*)g_h)[base >> 3]  = make_uint4(ph[0], ph[1], ph[2], ph[3]);
    ((uint4*)g_b2)[base >> 3] = make_uint4(pb[0], pb[1], pb[2], pb[3]);
}

// ---------------- GEMM + sigmoid ----------------
__global__ __launch_bounds__(256, 2)
void gemm_kernel(float* __restrict__ out) {
    extern __shared__ char smem[];
    const int tid  = threadIdx.x;
    const int lane = tid & 31;
    const int wid  = tid >> 5;
    const int wm   = wid & 3;   // 32-row block
    const int wn   = wid >> 2;  // 64-col block

    const int g  = blockIdx.y;
    const int it = c_it[blockIdx.x];
    const int jt = c_jt[blockIdx.x];
    const bool diag = (it == jt);

    const __half* __restrict__ Hi  = g_h  + ((size_t)g * NN + it * BM) * ND;
    const __half* __restrict__ B2i = g_b2 + ((size_t)g * NN + it * BM) * ND;
    const __half* __restrict__ Hj  = g_h  + ((size_t)g * NN + jt * BM) * ND;
    const __half* __restrict__ B2j = g_b2 + ((size_t)g * NN + jt * BM) * ND;

    const uint32_t s32 = cvta_smem(smem);
    // mats: 0=H_it, 1=B2_it, 2=H_jt, 3=B2_jt.  Diagonal: only 0,1 loaded;
    // single sweep uses b-frags from mat1 (B2 of the same block).
    const uint32_t b1_base = diag ? 1u * SMATC : 3u * SMATC;  // B2_jt
    const int nmat = diag ? 2 : 4;

    const int ld_row0 = tid >> 2;
    const int ld_seg  = tid & 3;

    float c[2][8][4];
#pragma unroll
    for (int mt = 0; mt < 2; mt++)
#pragma unroll
        for (int nt = 0; nt < 8; nt++)
#pragma unroll
            for (int q = 0; q < 4; q++) c[mt][nt][q] = 0.0f;

    const int la_r = lane & 15, la_s = lane >> 4;
    const int lb_r = ((lane >> 4) << 3) + (lane & 7), lb_s = (lane >> 3) & 1;

    auto issue_chunk = [&](int ch) {
        const uint32_t sb = s32 + (ch % NSTAGE) * SSTAGE;
        const int kofs = ch * BKC;
        for (int mat = 0; mat < nmat; mat++) {
            const __half* src =
                (mat == 0) ? Hi : (mat == 1) ? B2i : (mat == 2) ? Hj : B2j;
            const uint32_t mb = sb + mat * SMATC;
#pragma unroll
            for (int i2 = 0; i2 < 2; i2++) {
                const int row = ld_row0 + 64 * i2;
                const uint32_t dst = mb + swz(row, ld_seg);
                const void* s = src + (size_t)row * ND + kofs + ld_seg * 8;
                asm volatile("cp.async.cg.shared.global [%0], [%1], 16;"
                             :: "r"(dst), "l"(s) : "memory");
            }
        }
    };

    issue_chunk(0);
    asm volatile("cp.async.commit_group;" ::: "memory");
    issue_chunk(1);
    asm volatile("cp.async.commit_group;" ::: "memory");

    for (int ch = 0; ch < NCH; ch++) {
        asm volatile("cp.async.wait_group 1;" ::: "memory");
        __syncthreads();
        if (ch + 2 < NCH) issue_chunk(ch + 2);
        asm volatile("cp.async.commit_group;" ::: "memory");

        const uint32_t sb = s32 + (ch % NSTAGE) * SSTAGE;
#pragma unroll
        for (int h = 0; h < 2; h++) {
            uint32_t aH[2][4], aB2[2][4], bB2[16], bH[16];
            const int sega = 2 * h + la_s;
            const int segb = 2 * h + lb_s;
            // a-side frags (rows of the it-block)
#pragma unroll
            for (int mt = 0; mt < 2; mt++) {
                const int row = wm * 32 + mt * 16 + la_r;
                ldsm4(aH[mt], sb + 0 * SMATC + swz(row, sega));
                if (!diag)
                    ldsm4(aB2[mt], sb + 1 * SMATC + swz(row, sega));
            }
            // b-side frags
#pragma unroll
            for (int bt = 0; bt < 4; bt++) {
                const int row = wn * 64 + bt * 16 + lb_r;
                ldsm4(&bB2[bt * 4], sb + b1_base + swz(row, segb));
                if (!diag)
                    ldsm4(&bH[bt * 4], sb + 2 * SMATC + swz(row, segb));
            }
            // sweep 1: H_it * B2_jt^T
#pragma unroll
            for (int mt = 0; mt < 2; mt++)
#pragma unroll
                for (int nt = 0; nt < 8; nt++) {
                    const int bi = (nt >> 1) * 4 + (nt & 1) * 2;
                    mma16816(c[mt][nt], aH[mt], bB2[bi], bB2[bi + 1]);
                }
            // sweep 2 (off-diag only): B2_it * H_jt^T into SAME accumulator
            if (!diag) {
#pragma unroll
                for (int mt = 0; mt < 2; mt++)
#pragma unroll
                    for (int nt = 0; nt < 8; nt++) {
                        const int bi = (nt >> 1) * 4 + (nt & 1) * 2;
                        mma16816(c[mt][nt], aB2[mt], bH[bi], bH[bi + 1]);
                    }
            }
        }
    }

    // ---- epilogue ----
    // sC holds 0.5*acc (raw logits for off-diag; 0.5*D for diag, needing +T)
    __syncthreads();
    float* sC = (float*)smem;  // [128][132] = 67584 B
    const int r0  = wm * 32 + (lane >> 2);
    const int cn0 = wn * 64 + (lane & 3) * 2;
#pragma unroll
    for (int mt = 0; mt < 2; mt++)
#pragma unroll
        for (int nt = 0; nt < 8; nt++) {
            const int r  = r0 + mt * 16;
            const int cc = cn0 + nt * 8;
            sC[r * 132 + cc]           = 0.5f * c[mt][nt][0];
            sC[r * 132 + cc + 1]       = 0.5f * c[mt][nt][1];
            sC[(r + 8) * 132 + cc]     = 0.5f * c[mt][nt][2];
            sC[(r + 8) * 132 + cc + 1] = 0.5f * c[mt][nt][3];
        }
    __syncthreads();

    const int rbase = it * BM, cbase = jt * BM;
    if (!diag) {
        // direct store
        {
            const int r    = tid >> 1;
            const int colh = (tid & 1) * 64;
            float* dst = out + ((size_t)g * NN + rbase + r) * NN + cbase + colh;
            const float* srcr = sC + r * 132 + colh;
#pragma unroll
            for (int q = 0; q < 16; q++) {
                float4 v = ((const float4*)srcr)[q];
                v.x = fast_sigmoid(v.x); v.y = fast_sigmoid(v.y);
                v.z = fast_sigmoid(v.z); v.w = fast_sigmoid(v.w);
                ((float4*)dst)[q] = v;
            }
        }
        // transposed mirror store
        {
            const int col = tid >> 1;
            const int rh  = (tid & 1) * 64;
            float* dst = out + ((size_t)g * NN + cbase + col) * NN + rbase + rh;
#pragma unroll
            for (int q = 0; q < 16; q++) {
                float4 w;
                w.x = fast_sigmoid(sC[(rh + q * 4 + 0) * 132 + col]);
                w.y = fast_sigmoid(sC[(rh + q * 4 + 1) * 132 + col]);
                w.z = fast_sigmoid(sC[(rh + q * 4 + 2) * 132 + col]);
                w.w = fast_sigmoid(sC[(rh + q * 4 + 3) * 132 + col]);
                ((float4*)dst)[q] = w;
            }
        }
    } else {
        // diagonal: C = sigmoid(0.5*(D + D^T)) = sigmoid(sC[r][c] + sC[c][r])
        const int r    = tid >> 1;
        const int colh = (tid & 1) * 64;
        float* dst = out + ((size_t)g * NN + rbase + r) * NN + cbase + colh;
#pragma unroll
        for (int q = 0; q < 16; q++) {
            float4 w;
            const int c0 = colh + q * 4;
            w.x = fast_sigmoid(sC[r * 132 + c0 + 0] + sC[(c0 + 0) * 132 + r]);
            w.y = fast_sigmoid(sC[r * 132 + c0 + 1] + sC[(c0 + 1) * 132 + r]);
            w.z = fast_sigmoid(sC[r * 132 + c0 + 2] + sC[(c0 + 2) * 132 + r]);
            w.w = fast_sigmoid(sC[r * 132 + c0 + 3] + sC[(c0 + 3) * 132 + r]);
            ((float4*)dst)[q] = w;
        }
    }
}

extern "C" void kernel_launch(void* const* d_in, const int* in_sizes, int n_in,
                              void* d_out, int out_size) {
    const float* z = (const float*)d_in[0];
    float* out = (float*)d_out;
    // 128*512*256 floats / (8 per thread * 256 threads) = 8192 blocks
    convert_kernel<<<8192, 256>>>(z);
    cudaFuncSetAttribute(gemm_kernel, cudaFuncAttributeMaxDynamicSharedMemorySize,
                         SMEM_DYN);
    dim3 grid(NPAIR, 128);
    gemm_kernel<<<grid, 256, SMEM_DYN>>>(out);
}

// round 9
// speedup vs baseline: 2.6991x; 1.0528x over previous
#include <cuda_runtime.h>
#include <cuda_fp16.h>
#include <cstdint>

// out[g] = sigmoid(Z_g @ Z_g^T), G=128, N=512, D=256, fp32.
// R9: fp16 symmetrized 2-product (h = fp16(z), b2 = fp16(2z-h);
// 0.5*(H B2^T + B2 H^T) ~= Z Z^T). vs R8:
//  - 1-D grid, off-diag pairs first / diag pairs last (light tail wave)
//  - off-diag epilogue: direct tile stored from registers (STG.64),
//    sC holds sigmoided values so transpose pass is LDS+STG only.

namespace {
constexpr int NN = 512;
constexpr int ND = 256;
constexpr int BM = 128;
constexpr int NPAIR = 10;
constexpr int BKC = 32;                  // k elems per chunk (64B rows)
constexpr int NCH = ND / BKC;            // 8 chunks
constexpr int SMATC = BM * BKC * 2;      // 8192 B per operand mat per chunk
constexpr int SSTAGE = 4 * SMATC;        // 32768 B
constexpr int NSTAGE = 3;
constexpr int SMEM_DYN = NSTAGE * SSTAGE;  // 98304 B
}

// off-diagonal pairs first (heavy), diagonal last (light tail)
__constant__ int c_it[NPAIR] = {0,0,0,1,1,2, 0,1,2,3};
__constant__ int c_jt[NPAIR] = {1,2,3,2,3,3, 0,1,2,3};

__device__ __align__(16) __half g_h [(size_t)128 * 512 * 256];  // 32MB fp16(z)
__device__ __align__(16) __half g_b2[(size_t)128 * 512 * 256];  // 32MB fp16(2z-h)

__device__ __forceinline__ uint32_t cvta_smem(const void* p) {
    uint32_t a;
    asm("{ .reg .u64 t; cvta.to.shared.u64 t, %1; cvt.u32.u64 %0, t; }"
        : "=r"(a) : "l"(p));
    return a;
}

__device__ __forceinline__ uint32_t swz(int row, int seg) {
    return (uint32_t)(row * 64 + ((seg ^ ((row >> 1) & 3)) << 4));
}

__device__ __forceinline__ void ldsm4(uint32_t* r, uint32_t addr) {
    asm volatile("ldmatrix.sync.aligned.m8n8.x4.shared.b16 {%0,%1,%2,%3}, [%4];"
                 : "=r"(r[0]), "=r"(r[1]), "=r"(r[2]), "=r"(r[3]) : "r"(addr));
}

__device__ __forceinline__ void mma16816(float* c, const uint32_t* a,
                                         uint32_t b0, uint32_t b1) {
    asm volatile(
        "mma.sync.aligned.m16n8k16.row.col.f32.f16.f16.f32 "
        "{%0,%1,%2,%3}, {%4,%5,%6,%7}, {%8,%9}, {%0,%1,%2,%3};"
        : "+f"(c[0]), "+f"(c[1]), "+f"(c[2]), "+f"(c[3])
        : "r"(a[0]), "r"(a[1]), "r"(a[2]), "r"(a[3]), "r"(b0), "r"(b1));
}

__device__ __forceinline__ float fast_sigmoid(float x) {
    float e = __expf(-x);
    return __fdividef(1.0f, 1.0f + e);
}

// ---------------- pre-pass: fp32 -> fp16 h, fp16 b2 = fp16(2z - h) ----------------
__global__ __launch_bounds__(256)
void convert_kernel(const float* __restrict__ z) {
    const size_t base = ((size_t)blockIdx.x * blockDim.x + threadIdx.x) * 8;
    float x[8];
    *(float4*)&x[0] = *(const float4*)(z + base);
    *(float4*)&x[4] = *(const float4*)(z + base + 4);

    uint32_t ph[4], pb[4];
#pragma unroll
    for (int q = 0; q < 4; q++) {
        __half h0 = __float2half_rn(x[2 * q]);
        __half h1 = __float2half_rn(x[2 * q + 1]);
        float  f0 = __half2float(h0);
        float  f1 = __half2float(h1);
        __half b0 = __float2half_rn(2.0f * x[2 * q] - f0);
        __half b1 = __float2half_rn(2.0f * x[2 * q + 1] - f1);
        __half2 hp = __halves2half2(h0, h1);
        __half2 bp = __halves2half2(b0, b1);
        ph[q] = *(uint32_t*)&hp;
        pb[q] = *(uint32_t*)&bp;
    }
    ((uint4*)g_h)[base >> 3]  = make_uint4(ph[0], ph[1], ph[2], ph[3]);
    ((uint4*)g_b2)[base >> 3] = make_uint4(pb[0], pb[1], pb[2], pb[3]);
}

// ---------------- GEMM + sigmoid ----------------
__global__ __launch_bounds__(256, 2)
void gemm_kernel(float* __restrict__ out) {
    extern __shared__ char smem[];
    const int tid  = threadIdx.x;
    const int lane = tid & 31;
    const int wid  = tid >> 5;
    const int wm   = wid & 3;   // 32-row block
    const int wn   = wid >> 2;  // 64-col block

    const int bid = blockIdx.x;
    const int g   = bid & 127;
    const int p   = bid >> 7;
    const int it  = c_it[p];
    const int jt  = c_jt[p];
    const bool diag = (p >= 6);

    const __half* __restrict__ Hi  = g_h  + ((size_t)g * NN + it * BM) * ND;
    const __half* __restrict__ B2i = g_b2 + ((size_t)g * NN + it * BM) * ND;
    const __half* __restrict__ Hj  = g_h  + ((size_t)g * NN + jt * BM) * ND;
    const __half* __restrict__ B2j = g_b2 + ((size_t)g * NN + jt * BM) * ND;

    const uint32_t s32 = cvta_smem(smem);
    const uint32_t b1_base = diag ? 1u * SMATC : 3u * SMATC;  // B2_jt
    const int nmat = diag ? 2 : 4;

    const int ld_row0 = tid >> 2;
    const int ld_seg  = tid & 3;

    float c[2][8][4];
#pragma unroll
    for (int mt = 0; mt < 2; mt++)
#pragma unroll
        for (int nt = 0; nt < 8; nt++)
#pragma unroll
            for (int q = 0; q < 4; q++) c[mt][nt][q] = 0.0f;

    const int la_r = lane & 15, la_s = lane >> 4;
    const int lb_r = ((lane >> 4) << 3) + (lane & 7), lb_s = (lane >> 3) & 1;

    auto issue_chunk = [&](int ch) {
        const uint32_t sb = s32 + (ch % NSTAGE) * SSTAGE;
        const int kofs = ch * BKC;
        for (int mat = 0; mat < nmat; mat++) {
            const __half* src =
                (mat == 0) ? Hi : (mat == 1) ? B2i : (mat == 2) ? Hj : B2j;
            const uint32_t mb = sb + mat * SMATC;
#pragma unroll
            for (int i2 = 0; i2 < 2; i2++) {
                const int row = ld_row0 + 64 * i2;
                const uint32_t dst = mb + swz(row, ld_seg);
                const void* s = src + (size_t)row * ND + kofs + ld_seg * 8;
                asm volatile("cp.async.cg.shared.global [%0], [%1], 16;"
                             :: "r"(dst), "l"(s) : "memory");
            }
        }
    };

    issue_chunk(0);
    asm volatile("cp.async.commit_group;" ::: "memory");
    issue_chunk(1);
    asm volatile("cp.async.commit_group;" ::: "memory");

    for (int ch = 0; ch < NCH; ch++) {
        asm volatile("cp.async.wait_group 1;" ::: "memory");
        __syncthreads();
        if (ch + 2 < NCH) issue_chunk(ch + 2);
        asm volatile("cp.async.commit_group;" ::: "memory");

        const uint32_t sb = s32 + (ch % NSTAGE) * SSTAGE;
#pragma unroll
        for (int h = 0; h < 2; h++) {
            uint32_t aH[2][4], aB2[2][4], bB2[16], bH[16];
            const int sega = 2 * h + la_s;
            const int segb = 2 * h + lb_s;
#pragma unroll
            for (int mt = 0; mt < 2; mt++) {
                const int row = wm * 32 + mt * 16 + la_r;
                ldsm4(aH[mt], sb + 0 * SMATC + swz(row, sega));
                if (!diag)
                    ldsm4(aB2[mt], sb + 1 * SMATC + swz(row, sega));
            }
#pragma unroll
            for (int bt = 0; bt < 4; bt++) {
                const int row = wn * 64 + bt * 16 + lb_r;
                ldsm4(&bB2[bt * 4], sb + b1_base + swz(row, segb));
                if (!diag)
                    ldsm4(&bH[bt * 4], sb + 2 * SMATC + swz(row, segb));
            }
            // sweep 1: H_it * B2_jt^T
#pragma unroll
            for (int mt = 0; mt < 2; mt++)
#pragma unroll
                for (int nt = 0; nt < 8; nt++) {
                    const int bi = (nt >> 1) * 4 + (nt & 1) * 2;
                    mma16816(c[mt][nt], aH[mt], bB2[bi], bB2[bi + 1]);
                }
            // sweep 2 (off-diag only): B2_it * H_jt^T into SAME accumulator
            if (!diag) {
#pragma unroll
                for (int mt = 0; mt < 2; mt++)
#pragma unroll
                    for (int nt = 0; nt < 8; nt++) {
                        const int bi = (nt >> 1) * 4 + (nt & 1) * 2;
                        mma16816(c[mt][nt], aB2[mt], bH[bi], bH[bi + 1]);
                    }
            }
        }
    }

    // ---- epilogue ----
    __syncthreads();
    float* sC = (float*)smem;  // [128][132] = 67584 B
    const int rbase = it * BM, cbase = jt * BM;
    const int r0  = wm * 32 + (lane >> 2);
    const int cn0 = wn * 64 + (lane & 3) * 2;

    if (!diag) {
        // sigmoid on regs; direct tile stored from registers (float2),
        // sC gets the sigmoided values for the transpose pass.
#pragma unroll
        for (int mt = 0; mt < 2; mt++)
#pragma unroll
            for (int nt = 0; nt < 8; nt++) {
                const int r  = r0 + mt * 16;
                const int cc = cn0 + nt * 8;
                float s0 = fast_sigmoid(0.5f * c[mt][nt][0]);
                float s1 = fast_sigmoid(0.5f * c[mt][nt][1]);
                float s2 = fast_sigmoid(0.5f * c[mt][nt][2]);
                float s3 = fast_sigmoid(0.5f * c[mt][nt][3]);
                sC[r * 132 + cc]           = s0;
                sC[r * 132 + cc + 1]       = s1;
                sC[(r + 8) * 132 + cc]     = s2;
                sC[(r + 8) * 132 + cc + 1] = s3;
                float* d0 = out + ((size_t)g * NN + rbase + r) * NN + cbase + cc;
                float* d1 = out + ((size_t)g * NN + rbase + r + 8) * NN + cbase + cc;
                *(float2*)d0 = make_float2(s0, s1);
                *(float2*)d1 = make_float2(s2, s3);
            }
        __syncthreads();
        // transposed mirror store (values already sigmoided)
        const int col = tid >> 1;
        const int rh  = (tid & 1) * 64;
        float* dst = out + ((size_t)g * NN + cbase + col) * NN + rbase + rh;
#pragma unroll
        for (int q = 0; q < 16; q++) {
            float4 w;
            w.x = sC[(rh + q * 4 + 0) * 132 + col];
            w.y = sC[(rh + q * 4 + 1) * 132 + col];
            w.z = sC[(rh + q * 4 + 2) * 132 + col];
            w.w = sC[(rh + q * 4 + 3) * 132 + col];
            ((float4*)dst)[q] = w;
        }
    } else {
        // diag: sC holds 0.5*D; C = sigmoid(sC[r][c] + sC[c][r])
#pragma unroll
        for (int mt = 0; mt < 2; mt++)
#pragma unroll
            for (int nt = 0; nt < 8; nt++) {
                const int r  = r0 + mt * 16;
                const int cc = cn0 + nt * 8;
                sC[r * 132 + cc]           = 0.5f * c[mt][nt][0];
                sC[r * 132 + cc + 1]       = 0.5f * c[mt][nt][1];
                sC[(r + 8) * 132 + cc]     = 0.5f * c[mt][nt][2];
                sC[(r + 8) * 132 + cc + 1] = 0.5f * c[mt][nt][3];
            }
        __syncthreads();
        const int r    = tid >> 1;
        const int colh = (tid & 1) * 64;
        float* dst = out + ((size_t)g * NN + rbase + r) * NN + cbase + colh;
#pragma unroll
        for (int q = 0; q < 16; q++) {
            float4 w;
            const int c0 = colh + q * 4;
            w.x = fast_sigmoid(sC[r * 132 + c0 + 0] + sC[(c0 + 0) * 132 + r]);
            w.y = fast_sigmoid(sC[r * 132 + c0 + 1] + sC[(c0 + 1) * 132 + r]);
            w.z = fast_sigmoid(sC[r * 132 + c0 + 2] + sC[(c0 + 2) * 132 + r]);
            w.w = fast_sigmoid(sC[r * 132 + c0 + 3] + sC[(c0 + 3) * 132 + r]);
            ((float4*)dst)[q] = w;
        }
    }
}

extern "C" void kernel_launch(void* const* d_in, const int* in_sizes, int n_in,
                              void* d_out, int out_size) {
    const float* z = (const float*)d_in[0];
    float* out = (float*)d_out;
    convert_kernel<<<8192, 256>>>(z);
    cudaFuncSetAttribute(gemm_kernel, cudaFuncAttributeMaxDynamicSharedMemorySize,
                         SMEM_DYN);
    gemm_kernel<<<NPAIR * 128, 256, SMEM_DYN>>>(out);
}

// round 11
// speedup vs baseline: 4.0132x; 1.4868x over previous
#include <cuda_runtime.h>
#include <cuda_fp16.h>
#include <cstdint>

// out[g] = sigmoid(Z_g @ Z_g^T), G=128, N=512, D=256, fp32.
// R10: SINGLE fp16 product. h = fp16(z); logits ~= H H^T (fp32 accum).
// Error analysis (calibrated on R8): residual (HL^T + LH^T + LL^T) gives
// rel_err ~ 4.4e-4 < 1e-3. H H^T is exactly symmetric -> diagonal tiles
// need no symmetrization; mirror stores handle off-diagonal pairs.
// K-chunk=64 (2 mats/stage, 32KB), 3-stage cp.async ring, 10 of 16 pairs.

namespace {
constexpr int NN = 512;
constexpr int ND = 256;
constexpr int BM = 128;
constexpr int NPAIR = 10;
constexpr int BKC = 64;                   // k elems per chunk (128B rows)
constexpr int NCH = ND / BKC;             // 4 chunks
constexpr int SMATC = BM * BKC * 2;       // 16384 B per operand mat per chunk
constexpr int SSTAGE = 2 * SMATC;         // 32768 B (H_it, H_jt)
constexpr int NSTAGE = 3;
constexpr int SMEM_DYN = NSTAGE * SSTAGE; // 98304 B
}

// off-diagonal pairs first (heavier: 2 mats + mirror store), diagonal last
__constant__ int c_it[NPAIR] = {0,0,0,1,1,2, 0,1,2,3};
__constant__ int c_jt[NPAIR] = {1,2,3,2,3,3, 0,1,2,3};

__device__ __align__(16) __half g_h[(size_t)128 * 512 * 256];  // 32MB fp16(z)

__device__ __forceinline__ uint32_t cvta_smem(const void* p) {
    uint32_t a;
    asm("{ .reg .u64 t; cvta.to.shared.u64 t, %1; cvt.u32.u64 %0, t; }"
        : "=r"(a) : "l"(p));
    return a;
}

// 128B-row swizzle: seg (16B unit, 0..7) XOR low 3 bits of row
__device__ __forceinline__ uint32_t sw128(int row, int seg) {
    return (uint32_t)(row * 128 + ((seg ^ (row & 7)) << 4));
}

__device__ __forceinline__ void ldsm4(uint32_t* r, uint32_t addr) {
    asm volatile("ldmatrix.sync.aligned.m8n8.x4.shared.b16 {%0,%1,%2,%3}, [%4];"
                 : "=r"(r[0]), "=r"(r[1]), "=r"(r[2]), "=r"(r[3]) : "r"(addr));
}

__device__ __forceinline__ void mma16816(float* c, const uint32_t* a,
                                         uint32_t b0, uint32_t b1) {
    asm volatile(
        "mma.sync.aligned.m16n8k16.row.col.f32.f16.f16.f32 "
        "{%0,%1,%2,%3}, {%4,%5,%6,%7}, {%8,%9}, {%0,%1,%2,%3};"
        : "+f"(c[0]), "+f"(c[1]), "+f"(c[2]), "+f"(c[3])
        : "r"(a[0]), "r"(a[1]), "r"(a[2]), "r"(a[3]), "r"(b0), "r"(b1));
}

__device__ __forceinline__ float fast_sigmoid(float x) {
    float e = __expf(-x);
    return __fdividef(1.0f, 1.0f + e);
}

// ---------------- pre-pass: fp32 -> fp16 ----------------
__global__ __launch_bounds__(256)
void convert_kernel(const float* __restrict__ z) {
    const size_t base = ((size_t)blockIdx.x * blockDim.x + threadIdx.x) * 16;
#pragma unroll
    for (int u = 0; u < 2; u++) {
        float x[8];
        *(float4*)&x[0] = *(const float4*)(z + base + u * 8);
        *(float4*)&x[4] = *(const float4*)(z + base + u * 8 + 4);
        uint32_t ph[4];
#pragma unroll
        for (int q = 0; q < 4; q++) {
            __half2 hp = __floats2half2_rn(x[2 * q], x[2 * q + 1]);
            ph[q] = *(uint32_t*)&hp;
        }
        ((uint4*)g_h)[(base >> 3) + u] = make_uint4(ph[0], ph[1], ph[2], ph[3]);
    }
}

// ---------------- GEMM + sigmoid ----------------
__global__ __launch_bounds__(256, 2)
void gemm_kernel(float* __restrict__ out) {
    extern __shared__ char smem[];
    const int tid  = threadIdx.x;
    const int lane = tid & 31;
    const int wid  = tid >> 5;
    const int wm   = wid & 3;   // 32-row block
    const int wn   = wid >> 2;  // 64-col block

    const int bid = blockIdx.x;
    const int g   = bid & 127;
    const int p   = bid >> 7;
    const int it  = c_it[p];
    const int jt  = c_jt[p];
    const bool diag = (p >= 6);

    const __half* __restrict__ Hi = g_h + ((size_t)g * NN + it * BM) * ND;
    const __half* __restrict__ Hj = g_h + ((size_t)g * NN + jt * BM) * ND;

    const uint32_t s32 = cvta_smem(smem);
    const uint32_t b_base = diag ? 0u : SMATC;  // diag aliases B -> A
    const int nmat = diag ? 1 : 2;

    // loader: thread handles row = tid>>1, segs (tid&1)*4 + {0..3}
    const int ld_row = tid >> 1;
    const int ld_s4  = (tid & 1) * 4;

    float c[2][8][4];
#pragma unroll
    for (int mt = 0; mt < 2; mt++)
#pragma unroll
        for (int nt = 0; nt < 8; nt++)
#pragma unroll
            for (int q = 0; q < 4; q++) c[mt][nt][q] = 0.0f;

    const int la_r = lane & 15, la_s = lane >> 4;
    const int lb_r = ((lane >> 4) << 3) + (lane & 7), lb_s = (lane >> 3) & 1;

    auto issue_chunk = [&](int ch) {
        const uint32_t sb = s32 + (ch % NSTAGE) * SSTAGE;
        const int kofs = ch * BKC;
        for (int mat = 0; mat < nmat; mat++) {
            const __half* src = (mat == 0) ? Hi : Hj;
            const uint32_t mb = sb + mat * SMATC;
#pragma unroll
            for (int q = 0; q < 4; q++) {
                const int seg = ld_s4 + q;
                const uint32_t dst = mb + sw128(ld_row, seg);
                const void* s = src + (size_t)ld_row * ND + kofs + seg * 8;
                asm volatile("cp.async.cg.shared.global [%0], [%1], 16;"
                             :: "r"(dst), "l"(s) : "memory");
            }
        }
    };

    issue_chunk(0);
    asm volatile("cp.async.commit_group;" ::: "memory");
    issue_chunk(1);
    asm volatile("cp.async.commit_group;" ::: "memory");

    for (int ch = 0; ch < NCH; ch++) {
        asm volatile("cp.async.wait_group 1;" ::: "memory");
        __syncthreads();
        if (ch + 2 < NCH) issue_chunk(ch + 2);
        asm volatile("cp.async.commit_group;" ::: "memory");

        const uint32_t sb = s32 + (ch % NSTAGE) * SSTAGE;
#pragma unroll
        for (int s = 0; s < 4; s++) {           // k16 steps within chunk
            uint32_t aH[2][4], bH[16];
#pragma unroll
            for (int mt = 0; mt < 2; mt++) {
                const int row = wm * 32 + mt * 16 + la_r;
                ldsm4(aH[mt], sb + sw128(row, 2 * s + la_s));
            }
#pragma unroll
            for (int bt = 0; bt < 4; bt++) {
                const int row = wn * 64 + bt * 16 + lb_r;
                ldsm4(&bH[bt * 4], sb + b_base + sw128(row, 2 * s + lb_s));
            }
#pragma unroll
            for (int mt = 0; mt < 2; mt++)
#pragma unroll
                for (int nt = 0; nt < 8; nt++) {
                    const int bi = (nt >> 1) * 4 + (nt & 1) * 2;
                    mma16816(c[mt][nt], aH[mt], bH[bi], bH[bi + 1]);
                }
        }
    }

    // ---- epilogue ----
    const int rbase = it * BM, cbase = jt * BM;
    const int r0  = wm * 32 + (lane >> 2);
    const int cn0 = wn * 64 + (lane & 3) * 2;

    if (diag) {
        // H H^T symmetric: sigmoid + direct store only, no smem pass
#pragma unroll
        for (int mt = 0; mt < 2; mt++)
#pragma unroll
            for (int nt = 0; nt < 8; nt++) {
                const int r  = r0 + mt * 16;
                const int cc = cn0 + nt * 8;
                float s0 = fast_sigmoid(c[mt][nt][0]);
                float s1 = fast_sigmoid(c[mt][nt][1]);
                float s2 = fast_sigmoid(c[mt][nt][2]);
                float s3 = fast_sigmoid(c[mt][nt][3]);
                float* d0 = out + ((size_t)g * NN + rbase + r) * NN + cbase + cc;
                float* d1 = out + ((size_t)g * NN + rbase + r + 8) * NN + cbase + cc;
                *(float2*)d0 = make_float2(s0, s1);
                *(float2*)d1 = make_float2(s2, s3);
            }
        return;
    }

    __syncthreads();
    float* sC = (float*)smem;  // [128][132] = 67584 B
#pragma unroll
    for (int mt = 0; mt < 2; mt++)
#pragma unroll
        for (int nt = 0; nt < 8; nt++) {
            const int r  = r0 + mt * 16;
            const int cc = cn0 + nt * 8;
            float s0 = fast_sigmoid(c[mt][nt][0]);
            float s1 = fast_sigmoid(c[mt][nt][1]);
            float s2 = fast_sigmoid(c[mt][nt][2]);
            float s3 = fast_sigmoid(c[mt][nt][3]);
            sC[r * 132 + cc]           = s0;
            sC[r * 132 + cc + 1]       = s1;
            sC[(r + 8) * 132 + cc]     = s2;
            sC[(r + 8) * 132 + cc + 1] = s3;
            float* d0 = out + ((size_t)g * NN + rbase + r) * NN + cbase + cc;
            float* d1 = out + ((size_t)g * NN + rbase + r + 8) * NN + cbase + cc;
            *(float2*)d0 = make_float2(s0, s1);
            *(float2*)d1 = make_float2(s2, s3);
        }
    __syncthreads();
    // transposed mirror store (values already sigmoided)
    const int col = tid >> 1;
    const int rh  = (tid & 1) * 64;
    float* dst = out + ((size_t)g * NN + cbase + col) * NN + rbase + rh;
#pragma unroll
    for (int q = 0; q < 16; q++) {
        float4 w;
        w.x = sC[(rh + q * 4 + 0) * 132 + col];
        w.y = sC[(rh + q * 4 + 1) * 132 + col];
        w.z = sC[(rh + q * 4 + 2) * 132 + col];
        w.w = sC[(rh + q * 4 + 3) * 132 + col];
        ((float4*)dst)[q] = w;
    }
}

extern "C" void kernel_launch(void* const* d_in, const int* in_sizes, int n_in,
                              void* d_out, int out_size) {
    const float* z = (const float*)d_in[0];
    float* out = (float*)d_out;
    // 16,777,216 floats / (16 per thread * 256 threads) = 4096 blocks
    convert_kernel<<<4096, 256>>>(z);
    cudaFuncSetAttribute(gemm_kernel, cudaFuncAttributeMaxDynamicSharedMemorySize,
                         SMEM_DYN);
    gemm_kernel<<<NPAIR * 128, 256, SMEM_DYN>>>(out);
}

// round 14
// speedup vs baseline: 4.3682x; 1.0885x over previous
#include <cuda_runtime.h>
#include <cuda_fp16.h>
#include <cstdint>

// out[g] = sigmoid(Z_g @ Z_g^T), G=128, N=512, D=256, fp32.
// R11: single fp16 product (h = fp16(z); logits ~= H H^T, fp32 accum;
// rel_err ~4.4e-4, calibrated). vs R10:
//  - persistent 296-CTA grid (2/SM), cp.async ring continuous across tiles
//  - mirror (transposed) store directly from registers (no smem epilogue,
//    no epilogue barriers)

namespace {
constexpr int NN = 512;
constexpr int ND = 256;
constexpr int BM = 128;
constexpr int NPAIR = 10;
constexpr int NT   = NPAIR * 128;         // 1280 tiles
constexpr int NCTA = 296;                 // persistent CTAs (2 per SM)
constexpr int BKC = 64;                   // k elems per chunk (128B rows)
constexpr int NCH = ND / BKC;             // 4 chunks per tile
constexpr int SMATC = BM * BKC * 2;       // 16384 B per operand mat per chunk
constexpr int SSTAGE = 2 * SMATC;         // 32768 B (H_it, H_jt)
constexpr int NSTAGE = 3;
constexpr int SMEM_DYN = NSTAGE * SSTAGE; // 98304 B
}

// off-diagonal pairs first, diagonal last
__constant__ int c_it[NPAIR] = {0,0,0,1,1,2, 0,1,2,3};
__constant__ int c_jt[NPAIR] = {1,2,3,2,3,3, 0,1,2,3};

__device__ __align__(16) __half g_h[(size_t)128 * 512 * 256];  // 32MB fp16(z)

__device__ __forceinline__ uint32_t cvta_smem(const void* p) {
    uint32_t a;
    asm("{ .reg .u64 t; cvta.to.shared.u64 t, %1; cvt.u32.u64 %0, t; }"
        : "=r"(a) : "l"(p));
    return a;
}

// 128B-row swizzle: 16B seg index XOR low 3 bits of row
__device__ __forceinline__ uint32_t sw128(int row, int seg) {
    return (uint32_t)(row * 128 + ((seg ^ (row & 7)) << 4));
}

__device__ __forceinline__ void ldsm4(uint32_t* r, uint32_t addr) {
    asm volatile("ldmatrix.sync.aligned.m8n8.x4.shared.b16 {%0,%1,%2,%3}, [%4];"
                 : "=r"(r[0]), "=r"(r[1]), "=r"(r[2]), "=r"(r[3]) : "r"(addr));
}

__device__ __forceinline__ void mma16816(float* c, const uint32_t* a,
                                         uint32_t b0, uint32_t b1) {
    asm volatile(
        "mma.sync.aligned.m16n8k16.row.col.f32.f16.f16.f32 "
        "{%0,%1,%2,%3}, {%4,%5,%6,%7}, {%8,%9}, {%0,%1,%2,%3};"
        : "+f"(c[0]), "+f"(c[1]), "+f"(c[2]), "+f"(c[3])
        : "r"(a[0]), "r"(a[1]), "r"(a[2]), "r"(a[3]), "r"(b0), "r"(b1));
}

__device__ __forceinline__ float fast_sigmoid(float x) {
    float e = __expf(-x);
    return __fdividef(1.0f, 1.0f + e);
}

// ---------------- pre-pass: fp32 -> fp16 ----------------
__global__ __launch_bounds__(256)
void convert_kernel(const float* __restrict__ z) {
    const size_t base = ((size_t)blockIdx.x * blockDim.x + threadIdx.x) * 16;
#pragma unroll
    for (int u = 0; u < 2; u++) {
        float x[8];
        *(float4*)&x[0] = *(const float4*)(z + base + u * 8);
        *(float4*)&x[4] = *(const float4*)(z + base + u * 8 + 4);
        uint32_t ph[4];
#pragma unroll
        for (int q = 0; q < 4; q++) {
            __half2 hp = __floats2half2_rn(x[2 * q], x[2 * q + 1]);
            ph[q] = *(uint32_t*)&hp;
        }
        ((uint4*)g_h)[(base >> 3) + u] = make_uint4(ph[0], ph[1], ph[2], ph[3]);
    }
}

// ---------------- persistent GEMM + sigmoid ----------------
__global__ __launch_bounds__(256, 2)
void gemm_kernel(float* __restrict__ out) {
    extern __shared__ char smem[];
    const int tid  = threadIdx.x;
    const int lane = tid & 31;
    const int wid  = tid >> 5;
    const int wm   = wid & 3;   // 32-row block
    const int wn   = wid >> 2;  // 64-col block

    const int cta = blockIdx.x;
    const int nOwned = (NT - cta + NCTA - 1) / NCTA;
    const int totalChunks = nOwned * NCH;

    const uint32_t s32 = cvta_smem(smem);
    const int ld_row = tid >> 1;
    const int ld_s4  = (tid & 1) * 4;

    const int la_r = lane & 15, la_s = lane >> 4;
    const int lb_r = ((lane >> 4) << 3) + (lane & 7), lb_s = (lane >> 3) & 1;

    // seq = k*NCH + ch over this CTA's chunk list; stage = seq % NSTAGE
    auto issue_seq = [&](int seq) {
        const int k  = seq >> 2;           // NCH == 4
        const int ch = seq & 3;
        const int t  = cta + k * NCTA;
        const int p  = t >> 7;
        const int g  = t & 127;
        const bool dg = (p >= 6);
        const uint32_t sb = s32 + (seq % NSTAGE) * SSTAGE;
        const int kofs = ch * BKC;
        {
            const __half* Hi = g_h + ((size_t)g * NN + c_it[p] * BM) * ND;
#pragma unroll
            for (int q = 0; q < 4; q++) {
                const int seg = ld_s4 + q;
                const uint32_t dst = sb + sw128(ld_row, seg);
                const void* s = Hi + (size_t)ld_row * ND + kofs + seg * 8;
                asm volatile("cp.async.cg.shared.global [%0], [%1], 16;"
                             :: "r"(dst), "l"(s) : "memory");
            }
        }
        if (!dg) {
            const __half* Hj = g_h + ((size_t)g * NN + c_jt[p] * BM) * ND;
#pragma unroll
            for (int q = 0; q < 4; q++) {
                const int seg = ld_s4 + q;
                const uint32_t dst = sb + SMATC + sw128(ld_row, seg);
                const void* s = Hj + (size_t)ld_row * ND + kofs + seg * 8;
                asm volatile("cp.async.cg.shared.global [%0], [%1], 16;"
                             :: "r"(dst), "l"(s) : "memory");
            }
        }
    };

    // prologue: first two chunks
    issue_seq(0);
    asm volatile("cp.async.commit_group;" ::: "memory");
    issue_seq(1);
    asm volatile("cp.async.commit_group;" ::: "memory");
    int seq_load = 2;

    for (int k = 0; k < nOwned; k++) {
        const int t  = cta + k * NCTA;
        const int p  = t >> 7;
        const int g  = t & 127;
        const int it = c_it[p], jt = c_jt[p];
        const bool diag = (p >= 6);
        const uint32_t b_base = diag ? 0u : (uint32_t)SMATC;

        float c[2][8][4];
#pragma unroll
        for (int mt = 0; mt < 2; mt++)
#pragma unroll
            for (int nt = 0; nt < 8; nt++)
#pragma unroll
                for (int q = 0; q < 4; q++) c[mt][nt][q] = 0.0f;

        for (int ch = 0; ch < NCH; ch++) {
            asm volatile("cp.async.wait_group 1;" ::: "memory");
            __syncthreads();
            if (seq_load < totalChunks) issue_seq(seq_load);
            seq_load++;
            asm volatile("cp.async.commit_group;" ::: "memory");

            const uint32_t sb = s32 + ((k * NCH + ch) % NSTAGE) * SSTAGE;
#pragma unroll
            for (int s = 0; s < 4; s++) {     // k16 steps within chunk
                uint32_t aH[2][4], bH[16];
#pragma unroll
                for (int mt = 0; mt < 2; mt++) {
                    const int row = wm * 32 + mt * 16 + la_r;
                    ldsm4(aH[mt], sb + sw128(row, 2 * s + la_s));
                }
#pragma unroll
                for (int bt = 0; bt < 4; bt++) {
                    const int row = wn * 64 + bt * 16 + lb_r;
                    ldsm4(&bH[bt * 4], sb + b_base + sw128(row, 2 * s + lb_s));
                }
#pragma unroll
                for (int mt = 0; mt < 2; mt++)
#pragma unroll
                    for (int nt = 0; nt < 8; nt++) {
                        const int bi = (nt >> 1) * 4 + (nt & 1) * 2;
                        mma16816(c[mt][nt], aH[mt], bH[bi], bH[bi + 1]);
                    }
            }
        }

        // ---- epilogue: all stores directly from registers, no barriers ----
        const int rbase = it * BM, cbase = jt * BM;
        const int r0  = wm * 32 + (lane >> 2);
        const int cn0 = wn * 64 + (lane & 3) * 2;
        float* outg = out + (size_t)g * NN * NN;

#pragma unroll
        for (int mt = 0; mt < 2; mt++)
#pragma unroll
            for (int nt = 0; nt < 8; nt++) {
                const int r  = r0 + mt * 16;
                const int cc = cn0 + nt * 8;
                const float s0 = fast_sigmoid(c[mt][nt][0]);
                const float s1 = fast_sigmoid(c[mt][nt][1]);
                const float s2 = fast_sigmoid(c[mt][nt][2]);
                const float s3 = fast_sigmoid(c[mt][nt][3]);
                // direct tile (rbase+r, cbase+cc)
                float* d0 = outg + (size_t)(rbase + r) * NN + cbase + cc;
                float* d1 = outg + (size_t)(rbase + r + 8) * NN + cbase + cc;
                *(float2*)d0 = make_float2(s0, s1);
                *(float2*)d1 = make_float2(s2, s3);
                if (!diag) {
                    // mirror tile (cbase+cc, rbase+r): 32B-sector-forming STG.32
                    float* m0 = outg + (size_t)(cbase + cc) * NN + rbase;
                    float* m1 = m0 + NN;
                    m0[r] = s0; m0[r + 8] = s2;
                    m1[r] = s1; m1[r + 8] = s3;
                }
            }
    }
}

extern "C" void kernel_launch(void* const* d_in, const int* in_sizes, int n_in,
                              void* d_out, int out_size) {
    const float* z = (const float*)d_in[0];
    float* out = (float*)d_out;
    // 16,777,216 floats / (16 per thread * 256 threads) = 4096 blocks
    convert_kernel<<<4096, 256>>>(z);
    cudaFuncSetAttribute(gemm_kernel, cudaFuncAttributeMaxDynamicSharedMemorySize,
                         SMEM_DYN);
    gemm_kernel<<<NCTA, 256, SMEM_DYN>>>(out);
}

// round 15
// speedup vs baseline: 4.4737x; 1.0242x over previous
#include <cuda_runtime.h>
#include <cuda_fp16.h>
#include <cstdint>

// out[g] = sigmoid(Z_g @ Z_g^T), G=128, N=512, D=256, fp32.
// R15: single fp16 product (h = fp16(z); logits ~= H H^T, fp32 accum;
// rel_err 4.36e-4 calibrated). vs R14:
//  - warp specialization: 384-thread CTA = 256 consumer (8 warps, R14 tile
//    mapping) + 128 producer (cp.async + wait_group only)
//  - 1 CTA/SM (reg cap 170), 4-stage cp.async ring (128KB smem)
//  - one __syncthreads per chunk does the producer->consumer handoff

namespace {
constexpr int NN = 512;
constexpr int ND = 256;
constexpr int BM = 128;
constexpr int NPAIR = 10;
constexpr int NT   = NPAIR * 128;         // 1280 tiles
constexpr int NCTA = 148;                 // persistent, 1 per SM
constexpr int BKC = 64;                   // k elems per chunk (128B rows)
constexpr int NCH = ND / BKC;             // 4 chunks per tile
constexpr int SMATC = BM * BKC * 2;       // 16384 B per operand mat per chunk
constexpr int SSTAGE = 2 * SMATC;         // 32768 B (H_it, H_jt)
constexpr int NSTAGE = 4;
constexpr int SMEM_DYN = NSTAGE * SSTAGE; // 131072 B
}

// off-diagonal pairs first, diagonal last
__constant__ int c_it[NPAIR] = {0,0,0,1,1,2, 0,1,2,3};
__constant__ int c_jt[NPAIR] = {1,2,3,2,3,3, 0,1,2,3};

__device__ __align__(16) __half g_h[(size_t)128 * 512 * 256];  // 32MB fp16(z)

__device__ __forceinline__ uint32_t cvta_smem(const void* p) {
    uint32_t a;
    asm("{ .reg .u64 t; cvta.to.shared.u64 t, %1; cvt.u32.u64 %0, t; }"
        : "=r"(a) : "l"(p));
    return a;
}

// 128B-row swizzle: 16B seg index XOR low 3 bits of row
__device__ __forceinline__ uint32_t sw128(int row, int seg) {
    return (uint32_t)(row * 128 + ((seg ^ (row & 7)) << 4));
}

__device__ __forceinline__ void ldsm4(uint32_t* r, uint32_t addr) {
    asm volatile("ldmatrix.sync.aligned.m8n8.x4.shared.b16 {%0,%1,%2,%3}, [%4];"
                 : "=r"(r[0]), "=r"(r[1]), "=r"(r[2]), "=r"(r[3]) : "r"(addr));
}

__device__ __forceinline__ void mma16816(float* c, const uint32_t* a,
                                         uint32_t b0, uint32_t b1) {
    asm volatile(
        "mma.sync.aligned.m16n8k16.row.col.f32.f16.f16.f32 "
        "{%0,%1,%2,%3}, {%4,%5,%6,%7}, {%8,%9}, {%0,%1,%2,%3};"
        : "+f"(c[0]), "+f"(c[1]), "+f"(c[2]), "+f"(c[3])
        : "r"(a[0]), "r"(a[1]), "r"(a[2]), "r"(a[3]), "r"(b0), "r"(b1));
}

__device__ __forceinline__ float fast_sigmoid(float x) {
    float e = __expf(-x);
    return __fdividef(1.0f, 1.0f + e);
}

// ---------------- pre-pass: fp32 -> fp16 ----------------
__global__ __launch_bounds__(256)
void convert_kernel(const float* __restrict__ z) {
    const size_t base = ((size_t)blockIdx.x * blockDim.x + threadIdx.x) * 16;
#pragma unroll
    for (int u = 0; u < 2; u++) {
        float x[8];
        *(float4*)&x[0] = *(const float4*)(z + base + u * 8);
        *(float4*)&x[4] = *(const float4*)(z + base + u * 8 + 4);
        uint32_t ph[4];
#pragma unroll
        for (int q = 0; q < 4; q++) {
            __half2 hp = __floats2half2_rn(x[2 * q], x[2 * q + 1]);
            ph[q] = *(uint32_t*)&hp;
        }
        ((uint4*)g_h)[(base >> 3) + u] = make_uint4(ph[0], ph[1], ph[2], ph[3]);
    }
}

// ---------------- persistent warp-specialized GEMM + sigmoid ----------------
__global__ __launch_bounds__(384, 1)
void gemm_kernel(float* __restrict__ out) {
    extern __shared__ char smem[];
    const int tid = threadIdx.x;
    const bool producer = (tid >= 256);

    const int cta = blockIdx.x;
    const int nOwned = (NT - cta + NCTA - 1) / NCTA;   // tiles: t = cta + k*NCTA
    const int totalChunks = nOwned * NCH;
    const uint32_t s32 = cvta_smem(smem);

    // ---- producer state ----
    const int ptid = tid - 256;        // 0..127 (valid for producers)

    // ---- consumer state ----
    const int lane = tid & 31;
    const int wid  = tid >> 5;
    const int wm   = wid & 3;          // 32-row block
    const int wn   = wid >> 2;         // 64-col block
    const int la_r = lane & 15, la_s = lane >> 4;
    const int lb_r = ((lane >> 4) << 3) + (lane & 7), lb_s = (lane >> 3) & 1;

    float c[2][8][4];

    auto issue_seq = [&](int seq) {
        const int k  = seq >> 2;
        const int ch = seq & 3;
        const int t  = cta + k * NCTA;
        const int p  = t >> 7;
        const int g  = t & 127;
        const bool dg = (p >= 6);
        const uint32_t sb = s32 + (seq & 3) * SSTAGE;   // seq % NSTAGE
        const int kofs = ch * BKC;
        const int ni = dg ? 8 : 16;                     // diag: only mat 0
        const __half* base0 = g_h + ((size_t)g * NN + c_it[p] * BM) * ND;
        const __half* base1 = g_h + ((size_t)g * NN + c_jt[p] * BM) * ND;
        for (int i = 0; i < ni; i++) {
            const int tau = ptid + 128 * i;
            const int mat = tau >> 10;                  // 0 or 1
            const int row = (tau >> 3) & 127;
            const int seg = tau & 7;
            const __half* src = (mat ? base1 : base0) + (size_t)row * ND + kofs + seg * 8;
            const uint32_t dst = sb + mat * SMATC + sw128(row, seg);
            asm volatile("cp.async.cg.shared.global [%0], [%1], 16;"
                         :: "r"(dst), "l"(src) : "memory");
        }
    };

    // prologue: producers fill 3 stages ahead
    if (producer) {
        issue_seq(0);
        asm volatile("cp.async.commit_group;" ::: "memory");
        issue_seq(1);
        asm volatile("cp.async.commit_group;" ::: "memory");
        issue_seq(2);
        asm volatile("cp.async.commit_group;" ::: "memory");
    }

    for (int q = 0; q < totalChunks; q++) {
        if (producer) {
            // chunk q's group complete; q+1..q+2 may remain in flight
            asm volatile("cp.async.wait_group 2;" ::: "memory");
        }
        __syncthreads();   // handoff: data-for-q visible; stage (q+3)%4 free

        if (producer) {
            if (q + 3 < totalChunks) issue_seq(q + 3);
            asm volatile("cp.async.commit_group;" ::: "memory");  // keep group count aligned
        } else {
            const int k  = q >> 2;
            const int ch = q & 3;
            const int t  = cta + k * NCTA;
            const int p  = t >> 7;
            const bool diag = (p >= 6);
            const uint32_t b_base = diag ? 0u : (uint32_t)SMATC;
            const uint32_t sb = s32 + (q & 3) * SSTAGE;

            if (ch == 0) {
#pragma unroll
                for (int mt = 0; mt < 2; mt++)
#pragma unroll
                    for (int nt = 0; nt < 8; nt++)
#pragma unroll
                        for (int qq = 0; qq < 4; qq++) c[mt][nt][qq] = 0.0f;
            }

#pragma unroll
            for (int s = 0; s < 4; s++) {     // k16 steps within chunk
                uint32_t aH[2][4], bH[16];
#pragma unroll
                for (int mt = 0; mt < 2; mt++) {
                    const int row = wm * 32 + mt * 16 + la_r;
                    ldsm4(aH[mt], sb + sw128(row, 2 * s + la_s));
                }
#pragma unroll
                for (int bt = 0; bt < 4; bt++) {
                    const int row = wn * 64 + bt * 16 + lb_r;
                    ldsm4(&bH[bt * 4], sb + b_base + sw128(row, 2 * s + lb_s));
                }
#pragma unroll
                for (int mt = 0; mt < 2; mt++)
#pragma unroll
                    for (int nt = 0; nt < 8; nt++) {
                        const int bi = (nt >> 1) * 4 + (nt & 1) * 2;
                        mma16816(c[mt][nt], aH[mt], bH[bi], bH[bi + 1]);
                    }
            }

            if (ch == 3) {
                // ---- epilogue: all stores directly from registers ----
                const int g  = t & 127;
                const int it = c_it[p], jt = c_jt[p];
                const int rbase = it * BM, cbase = jt * BM;
                const int r0  = wm * 32 + (lane >> 2);
                const int cn0 = wn * 64 + (lane & 3) * 2;
                float* outg = out + (size_t)g * NN * NN;
#pragma unroll
                for (int mt = 0; mt < 2; mt++)
#pragma unroll
                    for (int nt = 0; nt < 8; nt++) {
                        const int r  = r0 + mt * 16;
                        const int cc = cn0 + nt * 8;
                        const float s0 = fast_sigmoid(c[mt][nt][0]);
                        const float s1 = fast_sigmoid(c[mt][nt][1]);
                        const float s2 = fast_sigmoid(c[mt][nt][2]);
                        const float s3 = fast_sigmoid(c[mt][nt][3]);
                        float* d0 = outg + (size_t)(rbase + r) * NN + cbase + cc;
                        float* d1 = outg + (size_t)(rbase + r + 8) * NN + cbase + cc;
                        *(float2*)d0 = make_float2(s0, s1);
                        *(float2*)d1 = make_float2(s2, s3);
                        if (!diag) {
                            float* m0 = outg + (size_t)(cbase + cc) * NN + rbase;
                            float* m1 = m0 + NN;
                            m0[r] = s0; m0[r + 8] = s2;
                            m1[r] = s1; m1[r + 8] = s3;
                        }
                    }
            }
        }
    }
}

extern "C" void kernel_launch(void* const* d_in, const int* in_sizes, int n_in,
                              void* d_out, int out_size) {
    const float* z = (const float*)d_in[0];
    float* out = (float*)d_out;
    // 16,777,216 floats / (16 per thread * 256 threads) = 4096 blocks
    convert_kernel<<<4096, 256>>>(z);
    cudaFuncSetAttribute(gemm_kernel, cudaFuncAttributeMaxDynamicSharedMemorySize,
                         SMEM_DYN);
    gemm_kernel<<<NCTA, 384, SMEM_DYN>>>(out);
}

// round 16
// speedup vs baseline: 4.6944x; 1.0493x over previous
#include <cuda_runtime.h>
#include <cuda_fp16.h>
#include <cstdint>

// out[g] = sigmoid(Z_g @ Z_g^T), G=128, N=512, D=256, fp32.
// R16: single fp16 product (h = fp16(z); logits ~= H H^T, fp32 accum).
// vs R15:
//  - sigmoid via HW tanh.approx (1 MUFU/elem instead of EX2+RCP)
//  - producer cp.async addressing made explicitly affine (const seg/xor/mat)

namespace {
constexpr int NN = 512;
constexpr int ND = 256;
constexpr int BM = 128;
constexpr int NPAIR = 10;
constexpr int NT   = NPAIR * 128;         // 1280 tiles
constexpr int NCTA = 148;                 // persistent, 1 per SM
constexpr int BKC = 64;                   // k elems per chunk (128B rows)
constexpr int NCH = ND / BKC;             // 4 chunks per tile
constexpr int SMATC = BM * BKC * 2;       // 16384 B per operand mat per chunk
constexpr int SSTAGE = 2 * SMATC;         // 32768 B (H_it, H_jt)
constexpr int NSTAGE = 4;
constexpr int SMEM_DYN = NSTAGE * SSTAGE; // 131072 B
}

// off-diagonal pairs first, diagonal last
__constant__ int c_it[NPAIR] = {0,0,0,1,1,2, 0,1,2,3};
__constant__ int c_jt[NPAIR] = {1,2,3,2,3,3, 0,1,2,3};

__device__ __align__(16) __half g_h[(size_t)128 * 512 * 256];  // 32MB fp16(z)

__device__ __forceinline__ uint32_t cvta_smem(const void* p) {
    uint32_t a;
    asm("{ .reg .u64 t; cvta.to.shared.u64 t, %1; cvt.u32.u64 %0, t; }"
        : "=r"(a) : "l"(p));
    return a;
}

// 128B-row swizzle: 16B seg index XOR low 3 bits of row
__device__ __forceinline__ uint32_t sw128(int row, int seg) {
    return (uint32_t)(row * 128 + ((seg ^ (row & 7)) << 4));
}

__device__ __forceinline__ void ldsm4(uint32_t* r, uint32_t addr) {
    asm volatile("ldmatrix.sync.aligned.m8n8.x4.shared.b16 {%0,%1,%2,%3}, [%4];"
                 : "=r"(r[0]), "=r"(r[1]), "=r"(r[2]), "=r"(r[3]) : "r"(addr));
}

__device__ __forceinline__ void mma16816(float* c, const uint32_t* a,
                                         uint32_t b0, uint32_t b1) {
    asm volatile(
        "mma.sync.aligned.m16n8k16.row.col.f32.f16.f16.f32 "
        "{%0,%1,%2,%3}, {%4,%5,%6,%7}, {%8,%9}, {%0,%1,%2,%3};"
        : "+f"(c[0]), "+f"(c[1]), "+f"(c[2]), "+f"(c[3])
        : "r"(a[0]), "r"(a[1]), "r"(a[2]), "r"(a[3]), "r"(b0), "r"(b1));
}

// sigmoid(x) = 0.5*tanh(0.5x) + 0.5  (HW MUFU.TANH, 1 MUFU per element)
__device__ __forceinline__ float fast_sigmoid(float x) {
    float t;
    asm("tanh.approx.f32 %0, %1;" : "=f"(t) : "f"(0.5f * x));
    return fmaf(0.5f, t, 0.5f);
}

// ---------------- pre-pass: fp32 -> fp16 ----------------
__global__ __launch_bounds__(256)
void convert_kernel(const float* __restrict__ z) {
    const size_t base = ((size_t)blockIdx.x * blockDim.x + threadIdx.x) * 16;
#pragma unroll
    for (int u = 0; u < 2; u++) {
        float x[8];
        *(float4*)&x[0] = *(const float4*)(z + base + u * 8);
        *(float4*)&x[4] = *(const float4*)(z + base + u * 8 + 4);
        uint32_t ph[4];
#pragma unroll
        for (int q = 0; q < 4; q++) {
            __half2 hp = __floats2half2_rn(x[2 * q], x[2 * q + 1]);
            ph[q] = *(uint32_t*)&hp;
        }
        ((uint4*)g_h)[(base >> 3) + u] = make_uint4(ph[0], ph[1], ph[2], ph[3]);
    }
}

// ---------------- persistent warp-specialized GEMM + sigmoid ----------------
__global__ __launch_bounds__(384, 1)
void gemm_kernel(float* __restrict__ out) {
    extern __shared__ char smem[];
    const int tid = threadIdx.x;
    const bool producer = (tid >= 256);

    const int cta = blockIdx.x;
    const int nOwned = (NT - cta + NCTA - 1) / NCTA;   // tiles: t = cta + k*NCTA
    const int totalChunks = nOwned * NCH;
    const uint32_t s32 = cvta_smem(smem);

    // ---- producer constants (affine decode: seg, row&7, xor-term fixed) ----
    const int ptid  = tid - 256;          // 0..127
    const int p_seg = ptid & 7;           // constant seg
    const int p_r0  = ptid >> 3;          // row0 (0..15); row_i = p_r0 + 16*(i&7)
    const uint32_t p_dst0 = sw128(p_r0, p_seg);  // base swizzled offset
    const int p_src0 = p_r0 * ND + p_seg * 8;    // element offset within mat

    // ---- consumer state ----
    const int lane = tid & 31;
    const int wid  = tid >> 5;
    const int wm   = wid & 3;
    const int wn   = wid >> 2;
    const int la_r = lane & 15, la_s = lane >> 4;
    const int lb_r = ((lane >> 4) << 3) + (lane & 7), lb_s = (lane >> 3) & 1;

    float c[2][8][4];

    auto issue_seq = [&](int seq) {
        const int k  = seq >> 2;
        const int ch = seq & 3;
        const int t  = cta + k * NCTA;
        const int p  = t >> 7;
        const int g  = t & 127;
        const bool dg = (p >= 6);
        const uint32_t sb = s32 + (seq & 3) * SSTAGE;
        const int kofs = ch * BKC;
        const __half* src0 = g_h + ((size_t)g * NN + c_it[p] * BM) * ND + kofs + p_src0;
        const uint32_t d0 = sb + p_dst0;
#pragma unroll
        for (int i = 0; i < 8; i++) {
            const uint32_t dst = d0 + (uint32_t)(i * 2048);
            const void* s = src0 + (size_t)i * 16 * ND;
            asm volatile("cp.async.cg.shared.global [%0], [%1], 16;"
                         :: "r"(dst), "l"(s) : "memory");
        }
        if (!dg) {
            const __half* src1 = g_h + ((size_t)g * NN + c_jt[p] * BM) * ND + kofs + p_src0;
            const uint32_t d1 = d0 + SMATC;
#pragma unroll
            for (int i = 0; i < 8; i++) {
                const uint32_t dst = d1 + (uint32_t)(i * 2048);
                const void* s = src1 + (size_t)i * 16 * ND;
                asm volatile("cp.async.cg.shared.global [%0], [%1], 16;"
                             :: "r"(dst), "l"(s) : "memory");
            }
        }
    };

    if (producer) {
        issue_seq(0);
        asm volatile("cp.async.commit_group;" ::: "memory");
        issue_seq(1);
        asm volatile("cp.async.commit_group;" ::: "memory");
        issue_seq(2);
        asm volatile("cp.async.commit_group;" ::: "memory");
    }

    for (int q = 0; q < totalChunks; q++) {
        if (producer) {
            asm volatile("cp.async.wait_group 2;" ::: "memory");
        }
        __syncthreads();   // handoff: data-for-q visible; stage (q+3)%4 free

        if (producer) {
            if (q + 3 < totalChunks) issue_seq(q + 3);
            asm volatile("cp.async.commit_group;" ::: "memory");
        } else {
            const int k  = q >> 2;
            const int ch = q & 3;
            const int t  = cta + k * NCTA;
            const int p  = t >> 7;
            const bool diag = (p >= 6);
            const uint32_t b_base = diag ? 0u : (uint32_t)SMATC;
            const uint32_t sb = s32 + (q & 3) * SSTAGE;

            if (ch == 0) {
#pragma unroll
                for (int mt = 0; mt < 2; mt++)
#pragma unroll
                    for (int nt = 0; nt < 8; nt++)
#pragma unroll
                        for (int qq = 0; qq < 4; qq++) c[mt][nt][qq] = 0.0f;
            }

#pragma unroll
            for (int s = 0; s < 4; s++) {     // k16 steps within chunk
                uint32_t aH[2][4], bH[16];
#pragma unroll
                for (int mt = 0; mt < 2; mt++) {
                    const int row = wm * 32 + mt * 16 + la_r;
                    ldsm4(aH[mt], sb + sw128(row, 2 * s + la_s));
                }
#pragma unroll
                for (int bt = 0; bt < 4; bt++) {
                    const int row = wn * 64 + bt * 16 + lb_r;
                    ldsm4(&bH[bt * 4], sb + b_base + sw128(row, 2 * s + lb_s));
                }
#pragma unroll
                for (int mt = 0; mt < 2; mt++)
#pragma unroll
                    for (int nt = 0; nt < 8; nt++) {
                        const int bi = (nt >> 1) * 4 + (nt & 1) * 2;
                        mma16816(c[mt][nt], aH[mt], bH[bi], bH[bi + 1]);
                    }
            }

            if (ch == 3) {
                // ---- epilogue: all stores directly from registers ----
                const int g  = t & 127;
                const int it = c_it[p], jt = c_jt[p];
                const int rbase = it * BM, cbase = jt * BM;
                const int r0  = wm * 32 + (lane >> 2);
                const int cn0 = wn * 64 + (lane & 3) * 2;
                float* outg = out + (size_t)g * NN * NN;
#pragma unroll
                for (int mt = 0; mt < 2; mt++)
#pragma unroll
                    for (int nt = 0; nt < 8; nt++) {
                        const int r  = r0 + mt * 16;
                        const int cc = cn0 + nt * 8;
                        const float s0 = fast_sigmoid(c[mt][nt][0]);
                        const float s1 = fast_sigmoid(c[mt][nt][1]);
                        const float s2 = fast_sigmoid(c[mt][nt][2]);
                        const float s3 = fast_sigmoid(c[mt][nt][3]);
                        float* d0 = outg + (size_t)(rbase + r) * NN + cbase + cc;
                        float* d1 = outg + (size_t)(rbase + r + 8) * NN + cbase + cc;
                        *(float2*)d0 = make_float2(s0, s1);
                        *(float2*)d1 = make_float2(s2, s3);
                        if (!diag) {
                            float* m0 = outg + (size_t)(cbase + cc) * NN + rbase;
                            float* m1 = m0 + NN;
                            m0[r] = s0; m0[r + 8] = s2;
                            m1[r] = s1; m1[r + 8] = s3;
                        }
                    }
            }
        }
    }
}

extern "C" void kernel_launch(void* const* d_in, const int* in_sizes, int n_in,
                              void* d_out, int out_size) {
    const float* z = (const float*)d_in[0];
    float* out = (float*)d_out;
    convert_kernel<<<4096, 256>>>(z);
    cudaFuncSetAttribute(gemm_kernel, cudaFuncAttributeMaxDynamicSharedMemorySize,
                         SMEM_DYN);
    gemm_kernel<<<NCTA, 384, SMEM_DYN>>>(out);
}

// round 17
// speedup vs baseline: 5.0511x; 1.0760x over previous
#include <cuda_runtime.h>
#include <cuda_fp16.h>
#include <cstdint>

// out[g] = sigmoid(Z_g @ Z_g^T), G=128, N=512, D=256, fp32.
// R17: single fp16 product (h = fp16(z); logits ~= H H^T, fp32 accum;
// rel_err 4.36e-4 calibrated). vs R16:
//  - K-chunk doubled to 128 (256B rows), 2-stage ring (same 128KB smem):
//    halves barrier/wait/handoff iterations per tile.

namespace {
constexpr int NN = 512;
constexpr int ND = 256;
constexpr int BM = 128;
constexpr int NPAIR = 10;
constexpr int NT   = NPAIR * 128;         // 1280 tiles
constexpr int NCTA = 148;                 // persistent, 1 per SM
constexpr int BKC = 128;                  // k elems per chunk (256B rows)
constexpr int NCH = ND / BKC;             // 2 chunks per tile
constexpr int SMATC = BM * BKC * 2;       // 32768 B per operand mat per chunk
constexpr int SSTAGE = 2 * SMATC;         // 65536 B (H_it, H_jt)
constexpr int NSTAGE = 2;
constexpr int SMEM_DYN = NSTAGE * SSTAGE; // 131072 B
}

// off-diagonal pairs first, diagonal last
__constant__ int c_it[NPAIR] = {0,0,0,1,1,2, 0,1,2,3};
__constant__ int c_jt[NPAIR] = {1,2,3,2,3,3, 0,1,2,3};

__device__ __align__(16) __half g_h[(size_t)128 * 512 * 256];  // 32MB fp16(z)

__device__ __forceinline__ uint32_t cvta_smem(const void* p) {
    uint32_t a;
    asm("{ .reg .u64 t; cvta.to.shared.u64 t, %1; cvt.u32.u64 %0, t; }"
        : "=r"(a) : "l"(p));
    return a;
}

// 256B-row swizzle: seg (16B unit, 0..15); keep seg bit3 (128B half),
// XOR low 3 seg bits with low 3 row bits (conflict-free ldmatrix + cp.async)
__device__ __forceinline__ uint32_t sw256(int row, int seg) {
    return (uint32_t)(row * 256 + ((seg & 8) << 4) + ((((seg ^ row) & 7)) << 4));
}

__device__ __forceinline__ void ldsm4(uint32_t* r, uint32_t addr) {
    asm volatile("ldmatrix.sync.aligned.m8n8.x4.shared.b16 {%0,%1,%2,%3}, [%4];"
                 : "=r"(r[0]), "=r"(r[1]), "=r"(r[2]), "=r"(r[3]) : "r"(addr));
}

__device__ __forceinline__ void mma16816(float* c, const uint32_t* a,
                                         uint32_t b0, uint32_t b1) {
    asm volatile(
        "mma.sync.aligned.m16n8k16.row.col.f32.f16.f16.f32 "
        "{%0,%1,%2,%3}, {%4,%5,%6,%7}, {%8,%9}, {%0,%1,%2,%3};"
        : "+f"(c[0]), "+f"(c[1]), "+f"(c[2]), "+f"(c[3])
        : "r"(a[0]), "r"(a[1]), "r"(a[2]), "r"(a[3]), "r"(b0), "r"(b1));
}

// sigmoid(x) = 0.5*tanh(0.5x) + 0.5  (HW MUFU.TANH)
__device__ __forceinline__ float fast_sigmoid(float x) {
    float t;
    asm("tanh.approx.f32 %0, %1;" : "=f"(t) : "f"(0.5f * x));
    return fmaf(0.5f, t, 0.5f);
}

// ---------------- pre-pass: fp32 -> fp16 ----------------
__global__ __launch_bounds__(256)
void convert_kernel(const float* __restrict__ z) {
    const size_t base = ((size_t)blockIdx.x * blockDim.x + threadIdx.x) * 16;
#pragma unroll
    for (int u = 0; u < 2; u++) {
        float x[8];
        *(float4*)&x[0] = *(const float4*)(z + base + u * 8);
        *(float4*)&x[4] = *(const float4*)(z + base + u * 8 + 4);
        uint32_t ph[4];
#pragma unroll
        for (int q = 0; q < 4; q++) {
            __half2 hp = __floats2half2_rn(x[2 * q], x[2 * q + 1]);
            ph[q] = *(uint32_t*)&hp;
        }
        ((uint4*)g_h)[(base >> 3) + u] = make_uint4(ph[0], ph[1], ph[2], ph[3]);
    }
}

// ---------------- persistent warp-specialized GEMM + sigmoid ----------------
__global__ __launch_bounds__(384, 1)
void gemm_kernel(float* __restrict__ out) {
    extern __shared__ char smem[];
    const int tid = threadIdx.x;
    const bool producer = (tid >= 256);

    const int cta = blockIdx.x;
    const int nOwned = (NT - cta + NCTA - 1) / NCTA;   // tiles: t = cta + k*NCTA
    const int totalChunks = nOwned * NCH;
    const uint32_t s32 = cvta_smem(smem);

    // ---- producer constants (affine: seg const, row&7 const) ----
    const int ptid  = tid - 256;           // 0..127
    const int p_seg = ptid & 15;           // 16B seg within 256B row
    const int p_r0  = ptid >> 4;           // 0..7; rows = p_r0 + 8*i
    const uint32_t p_dst0 = sw256(p_r0, p_seg);
    const int p_src0 = p_r0 * ND + p_seg * 8;    // halfs within mat chunk

    // ---- consumer state ----
    const int lane = tid & 31;
    const int wid  = tid >> 5;
    const int wm   = wid & 3;
    const int wn   = wid >> 2;
    const int la_r = lane & 15, la_s = lane >> 4;
    const int lb_r = ((lane >> 4) << 3) + (lane & 7), lb_s = (lane >> 3) & 1;

    float c[2][8][4];

    auto issue_seq = [&](int seq) {
        const int k  = seq >> 1;           // NCH == 2
        const int ch = seq & 1;
        const int t  = cta + k * NCTA;
        const int p  = t >> 7;
        const int g  = t & 127;
        const bool dg = (p >= 6);
        const uint32_t sb = s32 + (seq & 1) * SSTAGE;
        const int kofs = ch * BKC;
        const __half* src0 = g_h + ((size_t)g * NN + c_it[p] * BM) * ND + kofs + p_src0;
        const uint32_t d0 = sb + p_dst0;
#pragma unroll
        for (int i = 0; i < 16; i++) {     // rows p_r0 + 8*i
            const uint32_t dst = d0 + (uint32_t)(i * 2048);
            const void* s = src0 + (size_t)i * 8 * ND;
            asm volatile("cp.async.cg.shared.global [%0], [%1], 16;"
                         :: "r"(dst), "l"(s) : "memory");
        }
        if (!dg) {
            const __half* src1 = g_h + ((size_t)g * NN + c_jt[p] * BM) * ND + kofs + p_src0;
            const uint32_t d1 = d0 + SMATC;
#pragma unroll
            for (int i = 0; i < 16; i++) {
                const uint32_t dst = d1 + (uint32_t)(i * 2048);
                const void* s = src1 + (size_t)i * 8 * ND;
                asm volatile("cp.async.cg.shared.global [%0], [%1], 16;"
                             :: "r"(dst), "l"(s) : "memory");
            }
        }
    };

    if (producer) {
        issue_seq(0);
        asm volatile("cp.async.commit_group;" ::: "memory");
        asm volatile("cp.async.wait_group 0;" ::: "memory");
    }

    for (int q = 0; q < totalChunks; q++) {
        __syncthreads();   // data-for-q visible; stage (q+1)&1 free

        if (producer) {
            if (q + 1 < totalChunks) {
                issue_seq(q + 1);
                asm volatile("cp.async.commit_group;" ::: "memory");
                asm volatile("cp.async.wait_group 0;" ::: "memory");
            }
        } else {
            const int k  = q >> 1;
            const int ch = q & 1;
            const int t  = cta + k * NCTA;
            const int p  = t >> 7;
            const bool diag = (p >= 6);
            const uint32_t b_base = diag ? 0u : (uint32_t)SMATC;
            const uint32_t sb = s32 + (q & 1) * SSTAGE;

            if (ch == 0) {
#pragma unroll
                for (int mt = 0; mt < 2; mt++)
#pragma unroll
                    for (int nt = 0; nt < 8; nt++)
#pragma unroll
                        for (int qq = 0; qq < 4; qq++) c[mt][nt][qq] = 0.0f;
            }

#pragma unroll
            for (int s = 0; s < 8; s++) {     // k16 steps within 128-chunk
                uint32_t aH[2][4], bH[16];
                const int seg = 2 * s + la_s;
                const int segb = 2 * s + lb_s;
#pragma unroll
                for (int mt = 0; mt < 2; mt++) {
                    const int row = wm * 32 + mt * 16 + la_r;
                    ldsm4(aH[mt], sb + sw256(row, seg));
                }
#pragma unroll
                for (int bt = 0; bt < 4; bt++) {
                    const int row = wn * 64 + bt * 16 + lb_r;
                    ldsm4(&bH[bt * 4], sb + b_base + sw256(row, segb));
                }
#pragma unroll
                for (int mt = 0; mt < 2; mt++)
#pragma unroll
                    for (int nt = 0; nt < 8; nt++) {
                        const int bi = (nt >> 1) * 4 + (nt & 1) * 2;
                        mma16816(c[mt][nt], aH[mt], bH[bi], bH[bi + 1]);
                    }
            }

            if (ch == 1) {
                // ---- epilogue: all stores directly from registers ----
                const int g  = t & 127;
                const int it = c_it[p], jt = c_jt[p];
                const int rbase = it * BM, cbase = jt * BM;
                const int r0  = wm * 32 + (lane >> 2);
                const int cn0 = wn * 64 + (lane & 3) * 2;
                float* outg = out + (size_t)g * NN * NN;
#pragma unroll
                for (int mt = 0; mt < 2; mt++)
#pragma unroll
                    for (int nt = 0; nt < 8; nt++) {
                        const int r  = r0 + mt * 16;
                        const int cc = cn0 + nt * 8;
                        const float s0 = fast_sigmoid(c[mt][nt][0]);
                        const float s1 = fast_sigmoid(c[mt][nt][1]);
                        const float s2 = fast_sigmoid(c[mt][nt][2]);
                        const float s3 = fast_sigmoid(c[mt][nt][3]);
                        float* d0 = outg + (size_t)(rbase + r) * NN + cbase + cc;
                        float* d1 = outg + (size_t)(rbase + r + 8) * NN + cbase + cc;
                        *(float2*)d0 = make_float2(s0, s1);
                        *(float2*)d1 = make_float2(s2, s3);
                        if (!diag) {
                            float* m0 = outg + (size_t)(cbase + cc) * NN + rbase;
                            float* m1 = m0 + NN;
                            m0[r] = s0; m0[r + 8] = s2;
                            m1[r] = s1; m1[r + 8] = s3;
                        }
                    }
            }
        }
    }
}

extern "C" void kernel_launch(void* const* d_in, const int* in_sizes, int n_in,
                              void* d_out, int out_size) {
    const float* z = (const float*)d_in[0];
    float* out = (float*)d_out;
    convert_kernel<<<4096, 256>>>(z);
    cudaFuncSetAttribute(gemm_kernel, cudaFuncAttributeMaxDynamicSharedMemorySize,
                         SMEM_DYN);
    gemm_kernel<<<NCTA, 384, SMEM_DYN>>>(out);
}